// round 2
// baseline (speedup 1.0000x reference)
#include <cuda_runtime.h>
#include <cuda_bf16.h>

#define N_NODES 50000
#define N_EDGES 800000
#define D 128
#define NODE_BLOCKS 196   // ceil(N_NODES/256)

// ---------------- scratch (static device globals; no allocation) ----------------
__device__ int   g_deg[N_NODES];
__device__ float g_dinv[N_NODES];
__device__ int   g_off[N_NODES + 1];
__device__ int   g_cursor[N_NODES];
__device__ int   g_srcbuf[N_EDGES];
__device__ int   g_partial[NODE_BLOCKS];
__device__ float g_hs[(size_t)N_NODES * D];  // dinv-scaled GEMM output
__device__ float g_h1[(size_t)N_NODES * D];  // layer-1 activation

// ---------------- degree / CSR construction ----------------
__global__ void k_init() {
    int n = blockIdx.x * blockDim.x + threadIdx.x;
    if (n < N_NODES) { g_deg[n] = 1; g_cursor[n] = 0; }   // self-loop counts as 1
}

__global__ void k_count(const int* __restrict__ col) {
    int e = blockIdx.x * blockDim.x + threadIdx.x;
    if (e < N_EDGES) atomicAdd(&g_deg[col[e]], 1);
}

// per-block partial sums of edge counts (deg-1); also compute dinv
__global__ void k_scan1() {
    __shared__ int red[256];
    int t = threadIdx.x;
    int n = blockIdx.x * 256 + t;
    int deg = (n < N_NODES) ? g_deg[n] : 1;
    if (n < N_NODES) g_dinv[n] = rsqrtf((float)deg);
    red[t] = (n < N_NODES) ? deg - 1 : 0;
    __syncthreads();
    for (int s = 128; s > 0; s >>= 1) {
        if (t < s) red[t] += red[t + s];
        __syncthreads();
    }
    if (t == 0) g_partial[blockIdx.x] = red[0];
}

__global__ void k_scan2() {
    if (threadIdx.x == 0) {
        int s = 0;
        for (int i = 0; i < NODE_BLOCKS; i++) { int t = g_partial[i]; g_partial[i] = s; s += t; }
        g_off[N_NODES] = N_EDGES;
    }
}

__global__ void k_scan3() {
    __shared__ int sc[256];
    int t = threadIdx.x;
    int n = blockIdx.x * 256 + t;
    int v = (n < N_NODES) ? g_deg[n] - 1 : 0;
    sc[t] = v;
    __syncthreads();
    #pragma unroll
    for (int off = 1; off < 256; off <<= 1) {
        int x = (t >= off) ? sc[t - off] : 0;
        __syncthreads();
        sc[t] += x;
        __syncthreads();
    }
    if (n < N_NODES) g_off[n] = g_partial[blockIdx.x] + sc[t] - v;  // exclusive
}

__global__ void k_fill(const int* __restrict__ row, const int* __restrict__ col) {
    int e = blockIdx.x * blockDim.x + threadIdx.x;
    if (e < N_EDGES) {
        int c = col[e];
        int p = atomicAdd(&g_cursor[c], 1);
        g_srcbuf[g_off[c] + p] = row[e];
    }
}

// ---------------- GEMM: g_hs[r] = (A[r] @ W) * dinv[r] ----------------
// A = external x (layer 1, use_ext=1) or internal g_h1 (layer 2, use_ext=0).
// BM=128, BN=128(=full N), BK=8, TM=TN=8, 256 threads
__global__ __launch_bounds__(256, 2) void k_gemm_scale(const float* __restrict__ Aext,
                                                       int use_ext,
                                                       const float* __restrict__ W) {
    const float* __restrict__ A = use_ext ? Aext : (const float*)g_h1;
    __shared__ float As[8][128];
    __shared__ float Bs[8][128];
    int tid = threadIdx.x;
    int tx = tid & 15, ty = tid >> 4;
    int rowBase = blockIdx.x * 128;

    float acc[8][8];
    #pragma unroll
    for (int i = 0; i < 8; i++)
        #pragma unroll
        for (int j = 0; j < 8; j++) acc[i][j] = 0.f;

    int ar = tid >> 1;            // 0..127 : A tile row
    int ak = (tid & 1) * 4;       // 0 or 4 : A tile k offset
    int blin = tid * 4;
    int bk = blin >> 7;           // 0..7
    int bc = blin & 127;          // 0..124
    int gr = rowBase + ar;

    for (int k0 = 0; k0 < D; k0 += 8) {
        float4 av = (gr < N_NODES) ? *(const float4*)(A + (size_t)gr * D + k0 + ak)
                                   : make_float4(0.f, 0.f, 0.f, 0.f);
        As[ak + 0][ar] = av.x; As[ak + 1][ar] = av.y;
        As[ak + 2][ar] = av.z; As[ak + 3][ar] = av.w;
        *(float4*)(&Bs[bk][bc]) = *(const float4*)(W + (size_t)(k0 + bk) * D + bc);
        __syncthreads();
        #pragma unroll
        for (int k = 0; k < 8; k++) {
            float am[8], bn[8];
            #pragma unroll
            for (int i = 0; i < 8; i++) am[i] = As[k][ty * 8 + i];
            #pragma unroll
            for (int j = 0; j < 8; j++) bn[j] = Bs[k][tx * 8 + j];
            #pragma unroll
            for (int i = 0; i < 8; i++)
                #pragma unroll
                for (int j = 0; j < 8; j++) acc[i][j] += am[i] * bn[j];
        }
        __syncthreads();
    }

    #pragma unroll
    for (int i = 0; i < 8; i++) {
        int r = rowBase + ty * 8 + i;
        if (r < N_NODES) {
            float d = g_dinv[r];
            #pragma unroll
            for (int j = 0; j < 8; j += 4) {
                float4 o;
                o.x = acc[i][j + 0] * d;
                o.y = acc[i][j + 1] * d;
                o.z = acc[i][j + 2] * d;
                o.w = acc[i][j + 3] * d;
                *(float4*)(g_hs + (size_t)r * D + tx * 8 + j) = o;
            }
        }
    }
}

// ---------------- aggregation: one warp per target node ----------------
// dst[c] = prelu( dinv[c] * (g_hs[c] + sum_{r in csr[c]} g_hs[r]) + b )
// dst = external d_out (layer 2, use_ext=1) or internal g_h1 (layer 1, use_ext=0).
__global__ void k_agg(const float* __restrict__ bias, const float* __restrict__ alpha,
                      float* __restrict__ outExt, int use_ext) {
    float* __restrict__ dst = use_ext ? outExt : (float*)g_h1;
    int warp = (blockIdx.x * blockDim.x + threadIdx.x) >> 5;
    int lane = threadIdx.x & 31;
    if (warp >= N_NODES) return;
    int c = warp;
    const float* hs = (const float*)g_hs;

    float4 acc = ((const float4*)(hs + (size_t)c * D))[lane];  // self-loop term
    int beg = g_off[c], end = g_off[c + 1];
    for (int i = beg; i < end; i += 32) {
        int nb = end - i; if (nb > 32) nb = 32;
        int s = (lane < nb) ? g_srcbuf[i + lane] : 0;
        for (int j = 0; j < nb; j++) {
            int sj = __shfl_sync(0xffffffffu, s, j);
            float4 v = ((const float4*)(hs + (size_t)sj * D))[lane];
            acc.x += v.x; acc.y += v.y; acc.z += v.z; acc.w += v.w;
        }
    }
    float dc = g_dinv[c];
    float4 b = ((const float4*)bias)[lane];
    float4 a = ((const float4*)alpha)[lane];
    float4 o;
    o.x = fmaf(dc, acc.x, b.x);
    o.y = fmaf(dc, acc.y, b.y);
    o.z = fmaf(dc, acc.z, b.z);
    o.w = fmaf(dc, acc.w, b.w);
    o.x = o.x >= 0.f ? o.x : a.x * o.x;
    o.y = o.y >= 0.f ? o.y : a.y * o.y;
    o.z = o.z >= 0.f ? o.z : a.z * o.z;
    o.w = o.w >= 0.f ? o.w : a.w * o.w;
    ((float4*)(dst + (size_t)c * D))[lane] = o;
}

// ---------------- launch ----------------
extern "C" void kernel_launch(void* const* d_in, const int* in_sizes, int n_in,
                              void* d_out, int out_size) {
    const float* x  = (const float*)d_in[0];
    const int*   ei = (const int*)d_in[1];
    const float* W1 = (const float*)d_in[2];
    const float* b1 = (const float*)d_in[3];
    const float* a1 = (const float*)d_in[4];
    const float* W2 = (const float*)d_in[5];
    const float* b2 = (const float*)d_in[6];
    const float* a2 = (const float*)d_in[7];
    float* out = (float*)d_out;
    const int* row = ei;            // edge_index[0] : source
    const int* col = ei + N_EDGES;  // edge_index[1] : target

    const int EB = (N_EDGES + 255) / 256;       // 3125
    const int GB = (N_NODES + 127) / 128;       // 391
    const int AB = (N_NODES * 32 + 255) / 256;  // 6250

    // degree + CSR (shared by both layers)
    k_init <<<NODE_BLOCKS, 256>>>();
    k_count<<<EB, 256>>>(col);
    k_scan1<<<NODE_BLOCKS, 256>>>();
    k_scan2<<<1, 32>>>();
    k_scan3<<<NODE_BLOCKS, 256>>>();
    k_fill <<<EB, 256>>>(row, col);

    // layer 1: g_hs = (x@W1)*dinv ; g_h1 = agg(g_hs)
    k_gemm_scale<<<GB, 256>>>(x, 1, W1);
    k_agg       <<<AB, 256>>>(b1, a1, out, 0);
    // layer 2: g_hs = (g_h1@W2)*dinv ; out = agg(g_hs)
    k_gemm_scale<<<GB, 256>>>(x, 0, W2);
    k_agg       <<<AB, 256>>>(b2, a2, out, 1);
}

// round 4
// speedup vs baseline: 1.0044x; 1.0044x over previous
#include <cuda_runtime.h>
#include <cuda_fp16.h>

#define N_NODES 50000
#define N_EDGES 800000
#define D 128
#define NODE_BLOCKS 196   // ceil(N_NODES/256)

// ---------------- scratch (static device globals; no allocation) ----------------
__device__ int    g_deg[N_NODES];
__device__ float  g_dinv[N_NODES];
__device__ int    g_off[N_NODES + 1];
__device__ int    g_cursor[N_NODES];
__device__ int    g_srcbuf[N_EDGES];
__device__ int    g_partial[NODE_BLOCKS];
__device__ __half g_hs[(size_t)N_NODES * D];   // dinv-scaled GEMM output (fp16)
__device__ float  g_h1[(size_t)N_NODES * D];   // layer-1 activation (fp32)

// ---------------- degree / CSR construction ----------------
__global__ void k_init() {
    int n = blockIdx.x * blockDim.x + threadIdx.x;
    if (n < N_NODES) { g_deg[n] = 1; g_cursor[n] = 0; }   // self-loop counts as 1
}

__global__ void k_count(const int* __restrict__ col) {
    int e = blockIdx.x * blockDim.x + threadIdx.x;
    if (e < N_EDGES) atomicAdd(&g_deg[col[e]], 1);
}

// per-block partial sums of edge counts (deg-1); also compute dinv
__global__ void k_scan1() {
    __shared__ int red[256];
    int t = threadIdx.x;
    int n = blockIdx.x * 256 + t;
    int deg = (n < N_NODES) ? g_deg[n] : 1;
    if (n < N_NODES) g_dinv[n] = rsqrtf((float)deg);
    red[t] = (n < N_NODES) ? deg - 1 : 0;
    __syncthreads();
    for (int s = 128; s > 0; s >>= 1) {
        if (t < s) red[t] += red[t + s];
        __syncthreads();
    }
    if (t == 0) g_partial[blockIdx.x] = red[0];
}

// parallel exclusive scan of the 196 block partials (single 256-thread block)
__global__ void k_scan2() {
    __shared__ int sc[256];
    int t = threadIdx.x;
    int v = (t < NODE_BLOCKS) ? g_partial[t] : 0;
    sc[t] = v;
    __syncthreads();
    #pragma unroll
    for (int off = 1; off < 256; off <<= 1) {
        int x = (t >= off) ? sc[t - off] : 0;
        __syncthreads();
        sc[t] += x;
        __syncthreads();
    }
    if (t < NODE_BLOCKS) g_partial[t] = sc[t] - v;   // exclusive
    if (t == 0) g_off[N_NODES] = N_EDGES;
}

__global__ void k_scan3() {
    __shared__ int sc[256];
    int t = threadIdx.x;
    int n = blockIdx.x * 256 + t;
    int v = (n < N_NODES) ? g_deg[n] - 1 : 0;
    sc[t] = v;
    __syncthreads();
    #pragma unroll
    for (int off = 1; off < 256; off <<= 1) {
        int x = (t >= off) ? sc[t - off] : 0;
        __syncthreads();
        sc[t] += x;
        __syncthreads();
    }
    if (n < N_NODES) g_off[n] = g_partial[blockIdx.x] + sc[t] - v;  // exclusive
}

__global__ void k_fill(const int* __restrict__ row, const int* __restrict__ col) {
    int e = blockIdx.x * blockDim.x + threadIdx.x;
    if (e < N_EDGES) {
        int c = col[e];
        int p = atomicAdd(&g_cursor[c], 1);
        g_srcbuf[g_off[c] + p] = row[e];
    }
}

// ---------------- GEMM: g_hs[r] = fp16( (A[r] @ W) * dinv[r] ) ----------------
// A = external x (layer 1, use_ext=1) or internal g_h1 (layer 2, use_ext=0).
// BM=128, BN=128(=full N), BK=8, TM=TN=8, 256 threads
__global__ __launch_bounds__(256, 2) void k_gemm_scale(const float* __restrict__ Aext,
                                                       int use_ext,
                                                       const float* __restrict__ W) {
    const float* __restrict__ A = use_ext ? Aext : (const float*)g_h1;
    __shared__ float As[8][128];
    __shared__ float Bs[8][128];
    int tid = threadIdx.x;
    int tx = tid & 15, ty = tid >> 4;
    int rowBase = blockIdx.x * 128;

    float acc[8][8];
    #pragma unroll
    for (int i = 0; i < 8; i++)
        #pragma unroll
        for (int j = 0; j < 8; j++) acc[i][j] = 0.f;

    int ar = tid >> 1;            // 0..127 : A tile row
    int ak = (tid & 1) * 4;       // 0 or 4 : A tile k offset
    int blin = tid * 4;
    int bk = blin >> 7;           // 0..7
    int bc = blin & 127;          // 0..124
    int gr = rowBase + ar;

    for (int k0 = 0; k0 < D; k0 += 8) {
        float4 av = (gr < N_NODES) ? *(const float4*)(A + (size_t)gr * D + k0 + ak)
                                   : make_float4(0.f, 0.f, 0.f, 0.f);
        As[ak + 0][ar] = av.x; As[ak + 1][ar] = av.y;
        As[ak + 2][ar] = av.z; As[ak + 3][ar] = av.w;
        *(float4*)(&Bs[bk][bc]) = *(const float4*)(W + (size_t)(k0 + bk) * D + bc);
        __syncthreads();
        #pragma unroll
        for (int k = 0; k < 8; k++) {
            float am[8], bn[8];
            #pragma unroll
            for (int i = 0; i < 8; i++) am[i] = As[k][ty * 8 + i];
            #pragma unroll
            for (int j = 0; j < 8; j++) bn[j] = Bs[k][tx * 8 + j];
            #pragma unroll
            for (int i = 0; i < 8; i++)
                #pragma unroll
                for (int j = 0; j < 8; j++) acc[i][j] += am[i] * bn[j];
        }
        __syncthreads();
    }

    #pragma unroll
    for (int i = 0; i < 8; i++) {
        int r = rowBase + ty * 8 + i;
        if (r < N_NODES) {
            float d = g_dinv[r];
            __half2 h[4];
            #pragma unroll
            for (int j = 0; j < 4; j++)
                h[j] = __floats2half2_rn(acc[i][2 * j] * d, acc[i][2 * j + 1] * d);
            uint4 pk;
            pk.x = *(unsigned*)&h[0]; pk.y = *(unsigned*)&h[1];
            pk.z = *(unsigned*)&h[2]; pk.w = *(unsigned*)&h[3];
            *(uint4*)(g_hs + (size_t)r * D + tx * 8) = pk;   // 8 halves = 16B aligned
        }
    }
}

// ---------------- aggregation: one warp per target node ----------------
// dst[c] = prelu( dinv[c] * (hs[c] + sum_{r in csr[c]} hs[r]) + b )
// Each lane owns 4 features (4 halves = 8B per row).
__global__ void k_agg(const float* __restrict__ bias, const float* __restrict__ alpha,
                      float* __restrict__ outExt, int use_ext) {
    float* __restrict__ dst = use_ext ? outExt : (float*)g_h1;
    int warp = (blockIdx.x * blockDim.x + threadIdx.x) >> 5;
    int lane = threadIdx.x & 31;
    if (warp >= N_NODES) return;
    int c = warp;
    const uint2* hs = (const uint2*)g_hs;   // row stride = 32 uint2

    uint2 sv = hs[(size_t)c * 32 + lane];   // self-loop term
    float2 p0 = __half22float2(*(__half2*)&sv.x);
    float2 p1 = __half22float2(*(__half2*)&sv.y);
    float a0 = p0.x, a1 = p0.y, a2 = p1.x, a3 = p1.y;

    int beg = g_off[c], end = g_off[c + 1];
    for (int i = beg; i < end; i += 32) {
        int nb = end - i; if (nb > 32) nb = 32;
        int s = (lane < nb) ? g_srcbuf[i + lane] : 0;
        for (int j = 0; j < nb; j++) {
            int sj = __shfl_sync(0xffffffffu, s, j);
            uint2 v = hs[(size_t)sj * 32 + lane];
            float2 q0 = __half22float2(*(__half2*)&v.x);
            float2 q1 = __half22float2(*(__half2*)&v.y);
            a0 += q0.x; a1 += q0.y; a2 += q1.x; a3 += q1.y;
        }
    }
    float dc = g_dinv[c];
    float4 b = ((const float4*)bias)[lane];
    float4 al = ((const float4*)alpha)[lane];
    float4 o;
    o.x = fmaf(dc, a0, b.x);
    o.y = fmaf(dc, a1, b.y);
    o.z = fmaf(dc, a2, b.z);
    o.w = fmaf(dc, a3, b.w);
    o.x = o.x >= 0.f ? o.x : al.x * o.x;
    o.y = o.y >= 0.f ? o.y : al.y * o.y;
    o.z = o.z >= 0.f ? o.z : al.z * o.z;
    o.w = o.w >= 0.f ? o.w : al.w * o.w;
    ((float4*)(dst + (size_t)c * D))[lane] = o;
}

// ---------------- launch ----------------
extern "C" void kernel_launch(void* const* d_in, const int* in_sizes, int n_in,
                              void* d_out, int out_size) {
    const float* x  = (const float*)d_in[0];
    const int*   ei = (const int*)d_in[1];
    const float* W1 = (const float*)d_in[2];
    const float* b1 = (const float*)d_in[3];
    const float* a1 = (const float*)d_in[4];
    const float* W2 = (const float*)d_in[5];
    const float* b2 = (const float*)d_in[6];
    const float* a2 = (const float*)d_in[7];
    float* out = (float*)d_out;
    const int* row = ei;            // edge_index[0] : source
    const int* col = ei + N_EDGES;  // edge_index[1] : target

    const int EB = (N_EDGES + 255) / 256;       // 3125
    const int GB = (N_NODES + 127) / 128;       // 391
    const int AB = (N_NODES * 32 + 255) / 256;  // 6250

    // degree + CSR (shared by both layers)
    k_init <<<NODE_BLOCKS, 256>>>();
    k_count<<<EB, 256>>>(col);
    k_scan1<<<NODE_BLOCKS, 256>>>();
    k_scan2<<<1, 256>>>();
    k_scan3<<<NODE_BLOCKS, 256>>>();
    k_fill <<<EB, 256>>>(row, col);

    // layer 1: g_hs = fp16((x@W1)*dinv) ; g_h1 = agg(g_hs)
    k_gemm_scale<<<GB, 256>>>(x, 1, W1);
    k_agg       <<<AB, 256>>>(b1, a1, out, 0);
    // layer 2: g_hs = fp16((g_h1@W2)*dinv) ; out = agg(g_hs)
    k_gemm_scale<<<GB, 256>>>(x, 0, W2);
    k_agg       <<<AB, 256>>>(b2, a2, out, 1);
}